// round 1
// baseline (speedup 1.0000x reference)
#include <cuda_runtime.h>

// ---------------------------------------------------------------------------
// 2-layer LSTM (H=51) over T=2048 steps + 16 autoregressive future steps.
// B=512 independent sequences -> persistent kernel: 128 blocks x 4 batch each,
// one block per SM, all weights cached in shared memory, whole time loop
// inside one kernel launch (graph-capturable, allocation-free).
// ---------------------------------------------------------------------------

#define H    51
#define G    204            // 4*H gates
#define T    2048
#define FUT  16
#define TT   (T + FUT)
#define NB   4              // batch elements per block
#define NBLK 128            // 512 / NB
#define WP   52             // padded weight row pitch (floats, 16B-aligned rows)
#define GP   208            // gate buffer pitch
#define NTH  224            // 7 warps; threads 0..203 are workers
#define NCHUNK 13           // 52 / 4 float4 chunks per dot

// ---- shared memory layout (float indices; all float4 regions 16B aligned) ----
#define OFF_W1   0                        // Whh1 padded [204][52]
#define OFF_W2I  (OFF_W1  + G*WP)         // Wih2 padded
#define OFF_W2H  (OFF_W2I + G*WP)         // Whh2 padded
#define OFF_B1   (OFF_W2H + G*WP)         // b_ih1+b_hh1 [204]
#define OFF_B2   (OFF_B1 + G)             // b_ih2+b_hh2 [204]
#define OFF_WIH1 (OFF_B2 + G)             // W_ih1 [204]
#define OFF_WLIN (OFF_WIH1 + G)           // W_lin padded [52]
#define OFF_BLIN (OFF_WLIN + WP)          // b_lin (1) + 3 pad
#define OFF_H1   (OFF_BLIN + 4)           // h1 [4][52]
#define OFF_H2   (OFF_H1 + NB*WP)         // h2 [4][52]
#define OFF_GS   (OFF_H2 + NB*WP)         // gates [4][208]
#define OFF_RED  (OFF_GS + NB*GP)         // reduction scratch [208]
#define OFF_X    (OFF_RED + GP)           // current x [4]
#define OFF_OUT  (OFF_X + NB)             // last output [4]
#define SMEM_FLOATS (OFF_OUT + NB)

__device__ __forceinline__ float sigf(float x) {
    // sigmoid via MUFU.EX2 + MUFU.RCP; ~2^-21 accuracy
    return __fdividef(1.f, 1.f + __expf(-x));
}
__device__ __forceinline__ float tanh_fast(float x) {
    float xc = fminf(fmaxf(x, -15.f), 15.f);   // avoid inf/inf
    float e  = __expf(2.f * xc);
    return __fdividef(e - 1.f, e + 1.f);
}

__global__ __launch_bounds__(NTH, 1)
void lstm_persistent_kernel(const float* __restrict__ input,
                            const float* __restrict__ Wih1,
                            const float* __restrict__ Whh1,
                            const float* __restrict__ bih1,
                            const float* __restrict__ bhh1,
                            const float* __restrict__ Wih2,
                            const float* __restrict__ Whh2,
                            const float* __restrict__ bih2,
                            const float* __restrict__ bhh2,
                            const float* __restrict__ Wlin,
                            const float* __restrict__ blin,
                            float* __restrict__ out)
{
    extern __shared__ float sm[];
    const int j   = threadIdx.x;
    const int bb0 = blockIdx.x * NB;

    // ---------------- prologue: stage weights into shared ----------------
    for (int idx = j; idx < G * H; idx += NTH) {
        int r = idx / H, c = idx - r * H;
        sm[OFF_W1  + r * WP + c] = Whh1[idx];
        sm[OFF_W2I + r * WP + c] = Wih2[idx];
        sm[OFF_W2H + r * WP + c] = Whh2[idx];
    }
    for (int r = j; r < G; r += NTH) {
        sm[OFF_W1  + r * WP + H] = 0.f;     // pad column
        sm[OFF_W2I + r * WP + H] = 0.f;
        sm[OFF_W2H + r * WP + H] = 0.f;
        sm[OFF_B1 + r] = bih1[r] + bhh1[r];
        sm[OFF_B2 + r] = bih2[r] + bhh2[r];
        sm[OFF_WIH1 + r] = Wih1[r];
    }
    for (int c = j; c < WP; c += NTH)
        sm[OFF_WLIN + c] = (c < H) ? Wlin[c] : 0.f;
    if (j == 0) sm[OFF_BLIN] = blin[0];
    for (int idx = j; idx < NB * WP; idx += NTH) {
        sm[OFF_H1 + idx] = 0.f;
        sm[OFF_H2 + idx] = 0.f;
    }
    if (j < NB) {
        sm[OFF_X + j]   = input[(size_t)(bb0 + j) * T];   // x at t=0
        sm[OFF_OUT + j] = 0.f;
    }

    const int ub = (j < G) ? (j / H) : 0;   // batch owned in update phase
    const int uu = (j < G) ? (j % H) : 0;   // unit owned in update phase
    float c1 = 0.f, c2 = 0.f;               // cell states live in registers
    float xr = 0.f;                         // prefetched next input

    // ------------------------------ time loop ------------------------------
    for (int t = 0; t < TT; t++) {
        __syncthreads();                                        // (A)

        // prefetch next step's input (latency hidden under gate1+gate2)
        if (j >= G && j < G + NB) {
            int b = j - G;
            xr = (t + 1 < T) ? input[(size_t)(bb0 + b) * T + (t + 1)] : 0.f;
        }

        // ---- layer-1 gates: g1[j] = b1[j] + Wih1[j]*x + Whh1[j,:].h1 ----
        if (j < G) {
            const bool fut = (t >= T);
            const float wi = sm[OFF_WIH1 + j];
            const float bj = sm[OFF_B1 + j];
            float a[NB];
            #pragma unroll
            for (int b = 0; b < NB; b++) {
                float xv = fut ? sm[OFF_OUT + b] : sm[OFF_X + b];
                a[b] = bj + wi * xv;
            }
            const float* wrow = &sm[OFF_W1 + j * WP];
            #pragma unroll
            for (int kc = 0; kc < NCHUNK; kc++) {
                float4 wv = *(const float4*)(wrow + kc * 4);
                #pragma unroll
                for (int b = 0; b < NB; b++) {
                    float4 hv = *(const float4*)(&sm[OFF_H1 + b * WP + kc * 4]);
                    a[b] += wv.x * hv.x;
                    a[b] += wv.y * hv.y;
                    a[b] += wv.z * hv.z;
                    a[b] += wv.w * hv.w;
                }
            }
            #pragma unroll
            for (int b = 0; b < NB; b++)
                sm[OFF_GS + b * GP + j] = a[b];
        }
        __syncthreads();                                        // (B)

        // ---- layer-1 cell/hidden update (thread owns (ub, uu)) ----
        if (j < G) {
            const int gbase = OFF_GS + ub * GP;
            float gi = sm[gbase + uu];
            float gf = sm[gbase + H + uu];
            float gg = sm[gbase + 2 * H + uu];
            float go = sm[gbase + 3 * H + uu];
            c1 = sigf(gf) * c1 + sigf(gi) * tanh_fast(gg);
            float h = sigf(go) * tanh_fast(c1);
            sm[OFF_H1 + ub * WP + uu] = h;
        }
        __syncthreads();                                        // (C)

        // ---- layer-2 gates: g2[j] = b2[j] + Wih2[j,:].h1 + Whh2[j,:].h2 ----
        if (j < G) {
            const float bj = sm[OFF_B2 + j];
            float ai[NB], ah[NB];
            #pragma unroll
            for (int b = 0; b < NB; b++) { ai[b] = bj; ah[b] = 0.f; }
            const float* wi2 = &sm[OFF_W2I + j * WP];
            const float* wh2 = &sm[OFF_W2H + j * WP];
            #pragma unroll
            for (int kc = 0; kc < NCHUNK; kc++) {
                float4 w1 = *(const float4*)(wi2 + kc * 4);
                float4 w2 = *(const float4*)(wh2 + kc * 4);
                #pragma unroll
                for (int b = 0; b < NB; b++) {
                    float4 h1v = *(const float4*)(&sm[OFF_H1 + b * WP + kc * 4]);
                    float4 h2v = *(const float4*)(&sm[OFF_H2 + b * WP + kc * 4]);
                    ai[b] += w1.x * h1v.x;  ah[b] += w2.x * h2v.x;
                    ai[b] += w1.y * h1v.y;  ah[b] += w2.y * h2v.y;
                    ai[b] += w1.z * h1v.z;  ah[b] += w2.z * h2v.z;
                    ai[b] += w1.w * h1v.w;  ah[b] += w2.w * h2v.w;
                }
            }
            #pragma unroll
            for (int b = 0; b < NB; b++)
                sm[OFF_GS + b * GP + j] = ai[b] + ah[b];
        }
        __syncthreads();                                        // (D)

        // ---- layer-2 update + per-unit contribution to the output dot ----
        if (j < G) {
            const int gbase = OFF_GS + ub * GP;
            float gi = sm[gbase + uu];
            float gf = sm[gbase + H + uu];
            float gg = sm[gbase + 2 * H + uu];
            float go = sm[gbase + 3 * H + uu];
            c2 = sigf(gf) * c2 + sigf(gi) * tanh_fast(gg);
            float h = sigf(go) * tanh_fast(c2);
            sm[OFF_H2 + ub * WP + uu] = h;
            sm[OFF_RED + j] = sm[OFF_WLIN + uu] * h;   // Wlin[u]*h2[u]
        }
        __syncthreads();                                        // (E)

        // ---- output reduction: warp w reduces batch w's 51 products ----
        {
            int w = j >> 5;
            if (w < NB) {
                int ln = j & 31;
                int base = OFF_RED + w * H;
                float s = (ln < H) ? sm[base + ln] : 0.f;
                if (ln + 32 < H) s += sm[base + 32 + ln];
                #pragma unroll
                for (int m = 16; m; m >>= 1)
                    s += __shfl_xor_sync(0xffffffffu, s, m);
                if (ln == 0) {
                    float val = s + sm[OFF_BLIN];
                    sm[OFF_OUT + w] = val;                      // autoregressive feed
                    out[(size_t)(bb0 + w) * TT + t] = val;
                }
            }
        }
        // publish prefetched input for step t+1 (readers sync at top of loop)
        if (j >= G && j < G + NB) sm[OFF_X + (j - G)] = xr;
    }
}

extern "C" void kernel_launch(void* const* d_in, const int* in_sizes, int n_in,
                              void* d_out, int out_size)
{
    const float* input = (const float*)d_in[0];
    const float* Wih1  = (const float*)d_in[1];
    const float* Whh1  = (const float*)d_in[2];
    const float* bih1  = (const float*)d_in[3];
    const float* bhh1  = (const float*)d_in[4];
    const float* Wih2  = (const float*)d_in[5];
    const float* Whh2  = (const float*)d_in[6];
    const float* bih2  = (const float*)d_in[7];
    const float* bhh2  = (const float*)d_in[8];
    const float* Wlin  = (const float*)d_in[9];
    const float* blin  = (const float*)d_in[10];
    float* out = (float*)d_out;

    const size_t smem = SMEM_FLOATS * sizeof(float);   // ~136 KB
    cudaFuncSetAttribute(lstm_persistent_kernel,
                         cudaFuncAttributeMaxDynamicSharedMemorySize, (int)smem);

    lstm_persistent_kernel<<<NBLK, NTH, smem>>>(
        input, Wih1, Whh1, bih1, bhh1, Wih2, Whh2, bih2, bhh2, Wlin, blin, out);
}

// round 2
// speedup vs baseline: 1.2805x; 1.2805x over previous
#include <cuda_runtime.h>

// ---------------------------------------------------------------------------
// 2-layer LSTM (H=51) over T=2048 steps + 16 autoregressive future steps.
// Persistent kernel: 128 blocks x 4 batch, one block per SM.
// R1 -> R2: all weights live in REGISTERS (time-invariant, ~156 regs/thread,
// affordable at 7 warps/SM), gate dot products use packed fma.rn.f32x2 over k.
// Shared memory only holds h1/h2/gates/reduction scratch (~6 KB).
// ---------------------------------------------------------------------------

#define H    51
#define G    204            // 4*H gate rows
#define T    2048
#define FUT  16
#define TT   (T + FUT)
#define NB   4              // batch elements per block
#define NBLK 128            // 512 / NB
#define WP   52             // padded h row pitch (floats, 16B-aligned rows)
#define GP   208            // gate buffer pitch
#define NTH  224            // 7 warps; threads 0..203 are gate workers

// ---- shared memory layout (float indices; float4 regions 16B aligned) ----
#define OFF_H1   0                        // h1 [4][52]
#define OFF_H2   (OFF_H1 + NB*WP)         // h2 [4][52]
#define OFF_GS   (OFF_H2 + NB*WP)         // gates [4][208]
#define OFF_RED  (OFF_GS + NB*GP)         // reduction scratch [208]
#define OFF_X    (OFF_RED + GP)           // current x [4]
#define OFF_OUT  (OFF_X + NB)             // last output [4]
#define OFF_BLIN (OFF_OUT + NB)           // b_lin
#define SMEM_FLOATS (OFF_BLIN + 4)

typedef unsigned long long u64;

__device__ __forceinline__ u64 pack2(float lo, float hi) {
    u64 r; asm("mov.b64 %0, {%1,%2};" : "=l"(r) : "f"(lo), "f"(hi)); return r;
}
__device__ __forceinline__ u64 ffma2(u64 a, u64 b, u64 c) {
    u64 d; asm("fma.rn.f32x2 %0, %1, %2, %3;" : "=l"(d) : "l"(a), "l"(b), "l"(c));
    return d;
}
__device__ __forceinline__ float hsum2(u64 a) {
    float lo, hi; asm("mov.b64 {%0,%1}, %2;" : "=f"(lo), "=f"(hi) : "l"(a));
    return lo + hi;
}

__device__ __forceinline__ float sigf(float x) {
    return __fdividef(1.f, 1.f + __expf(-x));
}
__device__ __forceinline__ float tanh_fast(float x) {
    float xc = fminf(fmaxf(x, -15.f), 15.f);
    float e  = __expf(2.f * xc);
    return __fdividef(e - 1.f, e + 1.f);
}

__global__ __launch_bounds__(NTH, 1)
void lstm_persistent_kernel(const float* __restrict__ input,
                            const float* __restrict__ Wih1,
                            const float* __restrict__ Whh1,
                            const float* __restrict__ bih1,
                            const float* __restrict__ bhh1,
                            const float* __restrict__ Wih2,
                            const float* __restrict__ Whh2,
                            const float* __restrict__ bih2,
                            const float* __restrict__ bhh2,
                            const float* __restrict__ Wlin,
                            const float* __restrict__ blin,
                            float* __restrict__ out)
{
    __shared__ __align__(16) float sm[SMEM_FLOATS];
    const int j   = threadIdx.x;
    const int bb0 = blockIdx.x * NB;

    // ------------- prologue: weights into registers, states zero -------------
    u64 w1r[26], wi2r[26], wh2r[26];      // f32x2 pairs over k (k=51 padded w/ 0)
    float bj1 = 0.f, bj2 = 0.f, wi1 = 0.f, wlu = 0.f;
    const int ub = (j < G) ? (j / H) : 0;   // batch owned in update phase
    const int uu = (j < G) ? (j % H) : 0;   // unit owned in update phase

    if (j < G) {
        const float* r1 = Whh1 + j * H;
        const float* r2 = Wih2 + j * H;
        const float* r3 = Whh2 + j * H;
        #pragma unroll
        for (int p = 0; p < 26; p++) {
            int k0 = 2 * p, k1 = 2 * p + 1;
            float a1 = (k1 < H) ? r1[k1] : 0.f;
            float b1v = (k1 < H) ? r2[k1] : 0.f;
            float c1v = (k1 < H) ? r3[k1] : 0.f;
            w1r[p]  = pack2(r1[k0], a1);
            wi2r[p] = pack2(r2[k0], b1v);
            wh2r[p] = pack2(r3[k0], c1v);
        }
        bj1 = bih1[j] + bhh1[j];
        bj2 = bih2[j] + bhh2[j];
        wi1 = Wih1[j];
        wlu = Wlin[uu];
    }

    for (int idx = j; idx < NB * WP; idx += NTH) {
        sm[OFF_H1 + idx] = 0.f;
        sm[OFF_H2 + idx] = 0.f;
    }
    if (j < NB) {
        sm[OFF_X + j]   = input[(size_t)(bb0 + j) * T];   // x at t=0
        sm[OFF_OUT + j] = 0.f;
    }
    if (j == 0) sm[OFF_BLIN] = blin[0];

    float c1 = 0.f, c2 = 0.f;               // cell states in registers
    float xr = 0.f;                         // prefetched next input

    // ------------------------------ time loop ------------------------------
    for (int t = 0; t < TT; t++) {
        __syncthreads();                                        // (A)

        // prefetch next step's input (hidden under the gate phases)
        if (j >= G && j < G + NB) {
            int b = j - G;
            xr = (t + 1 < T) ? input[(size_t)(bb0 + b) * T + (t + 1)] : 0.f;
        }

        // ---- layer-1 gates: g1[j] = b1 + Wih1[j]*x + Whh1[j,:].h1 ----
        if (j < G) {
            const bool fut = (t >= T);
            u64 acc[NB];
            #pragma unroll
            for (int b = 0; b < NB; b++) {
                float xv = fut ? sm[OFF_OUT + b] : sm[OFF_X + b];
                acc[b] = pack2(fmaf(wi1, xv, bj1), 0.f);
            }
            #pragma unroll
            for (int p = 0; p < 13; p++) {
                #pragma unroll
                for (int b = 0; b < NB; b++) {
                    ulonglong2 hv = *(const ulonglong2*)(&sm[OFF_H1 + b * WP + p * 4]);
                    acc[b] = ffma2(w1r[2 * p],     hv.x, acc[b]);
                    acc[b] = ffma2(w1r[2 * p + 1], hv.y, acc[b]);
                }
            }
            #pragma unroll
            for (int b = 0; b < NB; b++)
                sm[OFF_GS + b * GP + j] = hsum2(acc[b]);
        }
        __syncthreads();                                        // (B)

        // ---- layer-1 cell/hidden update (thread owns (ub, uu)) ----
        if (j < G) {
            const int gbase = OFF_GS + ub * GP;
            float gi = sm[gbase + uu];
            float gf = sm[gbase + H + uu];
            float gg = sm[gbase + 2 * H + uu];
            float go = sm[gbase + 3 * H + uu];
            c1 = sigf(gf) * c1 + sigf(gi) * tanh_fast(gg);
            float h = sigf(go) * tanh_fast(c1);
            sm[OFF_H1 + ub * WP + uu] = h;
        }
        __syncthreads();                                        // (C)

        // ---- layer-2 gates: g2[j] = b2 + Wih2[j,:].h1 + Whh2[j,:].h2 ----
        if (j < G) {
            u64 acc[NB];
            #pragma unroll
            for (int b = 0; b < NB; b++) acc[b] = pack2(bj2, 0.f);
            #pragma unroll
            for (int p = 0; p < 13; p++) {
                #pragma unroll
                for (int b = 0; b < NB; b++) {
                    ulonglong2 h1v = *(const ulonglong2*)(&sm[OFF_H1 + b * WP + p * 4]);
                    ulonglong2 h2v = *(const ulonglong2*)(&sm[OFF_H2 + b * WP + p * 4]);
                    acc[b] = ffma2(wi2r[2 * p],     h1v.x, acc[b]);
                    acc[b] = ffma2(wi2r[2 * p + 1], h1v.y, acc[b]);
                    acc[b] = ffma2(wh2r[2 * p],     h2v.x, acc[b]);
                    acc[b] = ffma2(wh2r[2 * p + 1], h2v.y, acc[b]);
                }
            }
            #pragma unroll
            for (int b = 0; b < NB; b++)
                sm[OFF_GS + b * GP + j] = hsum2(acc[b]);
        }
        __syncthreads();                                        // (D)

        // ---- layer-2 update + per-unit contribution to the output dot ----
        if (j < G) {
            const int gbase = OFF_GS + ub * GP;
            float gi = sm[gbase + uu];
            float gf = sm[gbase + H + uu];
            float gg = sm[gbase + 2 * H + uu];
            float go = sm[gbase + 3 * H + uu];
            c2 = sigf(gf) * c2 + sigf(gi) * tanh_fast(gg);
            float h = sigf(go) * tanh_fast(c2);
            sm[OFF_H2 + ub * WP + uu] = h;
            sm[OFF_RED + j] = wlu * h;       // Wlin[u]*h2[u]
        }
        __syncthreads();                                        // (E)

        // ---- output reduction: warp w reduces batch w's 51 products ----
        {
            int w = j >> 5;
            if (w < NB) {
                int ln = j & 31;
                int base = OFF_RED + w * H;
                float s = (ln < H) ? sm[base + ln] : 0.f;
                if (ln + 32 < H) s += sm[base + 32 + ln];
                #pragma unroll
                for (int m = 16; m; m >>= 1)
                    s += __shfl_xor_sync(0xffffffffu, s, m);
                if (ln == 0) {
                    float val = s + sm[OFF_BLIN];
                    sm[OFF_OUT + w] = val;                      // autoregressive feed
                    out[(size_t)(bb0 + w) * TT + t] = val;
                }
            }
        }
        // publish prefetched input for step t+1 (readers sync at top of loop)
        if (j >= G && j < G + NB) sm[OFF_X + (j - G)] = xr;
    }
}

extern "C" void kernel_launch(void* const* d_in, const int* in_sizes, int n_in,
                              void* d_out, int out_size)
{
    const float* input = (const float*)d_in[0];
    const float* Wih1  = (const float*)d_in[1];
    const float* Whh1  = (const float*)d_in[2];
    const float* bih1  = (const float*)d_in[3];
    const float* bhh1  = (const float*)d_in[4];
    const float* Wih2  = (const float*)d_in[5];
    const float* Whh2  = (const float*)d_in[6];
    const float* bih2  = (const float*)d_in[7];
    const float* bhh2  = (const float*)d_in[8];
    const float* Wlin  = (const float*)d_in[9];
    const float* blin  = (const float*)d_in[10];
    float* out = (float*)d_out;

    lstm_persistent_kernel<<<NBLK, NTH>>>(
        input, Wih1, Whh1, bih1, bhh1, Wih2, Whh2, bih2, bhh2, Wlin, blin, out);
}